// round 14
// baseline (speedup 1.0000x reference)
#include <cuda_runtime.h>
#include <cuda_bf16.h>

#define N_   20000
#define E_   320000
#define B_   128
#define L_   2
#define SLOPE 0.2f
#define EPS_  1e-5f

// ---------------- scratch (static device allocations) ----------------
__device__ int   g_counts[N_];        // zero at load; re-zeroed by scan each call
__device__ int   g_rowptr[N_ + 1];
__device__ int   g_cursor[N_];
__device__ int   g_csr_src[E_];

__device__ float g_wea[L_][128][2];   // collapsed W_e * att_e
__device__ float g_inse[L_][B_][2];   // ins part of ae per graph

__device__ float2 g_aet[L_][E_];      // edge attention term, EDGE order (pre-permute)
__device__ float2 g_ae[L_][E_];       // edge attention term, CSR order (post-permute)
__device__ float g_xl[(size_t)N_ * 128];
__device__ float g_alr[N_ * 4];       // al0, al1, ar0, ar1
__device__ float g_h[(size_t)N_ * 64];
__device__ float g_bnstats[128];      // sum[64], sumsq[64]; re-zeroed by scan

// ---------------- CSR build ----------------
__global__ void hist_kernel(const int* __restrict__ dst) {
    int i = blockIdx.x * blockDim.x + threadIdx.x;
    if (i < E_) atomicAdd(&g_counts[dst[i]], 1);
}

// single block, 1024 threads; also re-zeroes g_counts + g_bnstats
__global__ void scan_kernel() {
    __shared__ int sums[1024];
    const int C = 20;                  // 1024*20 = 20480 >= N_
    int t = threadIdx.x;
    int base = t * C;
    int vals[C];
    int run = 0;
    #pragma unroll
    for (int i = 0; i < C; i++) {
        int idx = base + i;
        int v = (idx < N_) ? g_counts[idx] : 0;
        run += v;
        vals[i] = run;                 // thread-local inclusive
    }
    sums[t] = run;
    __syncthreads();
    for (int o = 1; o < 1024; o <<= 1) {
        int x = (t >= o) ? sums[t - o] : 0;
        __syncthreads();
        sums[t] += x;
        __syncthreads();
    }
    int off = sums[t] - run;
    if (t == 0) g_rowptr[0] = 0;
    #pragma unroll
    for (int i = 0; i < C; i++) {
        int idx = base + i;
        if (idx < N_) {
            int incl = off + vals[i];
            int cnt  = vals[i] - (i ? vals[i - 1] : 0);
            g_rowptr[idx + 1] = incl;
            g_cursor[idx]     = incl - cnt;
            g_counts[idx]     = 0;     // restore invariant for next call
        }
    }
    if (t < 128) g_bnstats[t] = 0.f;
}

// scatter: builds CSR src list AND permutes the edge-order ae values into CSR order
__global__ void scatter_kernel(const int* __restrict__ src, const int* __restrict__ dst) {
    int i = blockIdx.x * blockDim.x + threadIdx.x;
    if (i < E_) {
        int d = dst[i];
        float2 a0 = g_aet[0][i];
        float2 a1 = g_aet[1][i];
        int pos = atomicAdd(&g_cursor[d], 1);
        g_csr_src[pos] = src[i];
        g_ae[0][pos] = a0;
        g_ae[1][pos] = a1;
    }
}

// ---------------- setup1: collapse W_e*att_e — 64 blocks, warp-per-output ----------------
__global__ void setup1_kernel(const float* __restrict__ W_e,
                              const float* __restrict__ att_e) {
    int warp = (blockIdx.x * blockDim.x + threadIdx.x) >> 5;
    int lane = threadIdx.x & 31;
    if (warp >= L_ * 128 * 2) return;  // 512 outputs
    int l = warp >> 8;
    int k = (warp >> 1) & 127;
    int h = warp & 1;
    const float* wrow = W_e + ((size_t)l * 128 + k) * 128 + h * 64;
    const float* arow = att_e + l * 128 + h * 64;
    float s = wrow[lane] * arow[lane] + wrow[lane + 32] * arow[lane + 32];
    #pragma unroll
    for (int o = 16; o; o >>= 1) s += __shfl_xor_sync(0xffffffffu, s, o);
    if (lane == 0) g_wea[l][k][h] = s;
}

// ---------------- setup2: per-graph ins dots — 64 blocks, warp-per-output ----------------
__global__ void setup2_kernel(const float* __restrict__ instr) {
    int warp = (blockIdx.x * blockDim.x + threadIdx.x) >> 5;
    int lane = threadIdx.x & 31;
    if (warp >= L_ * B_ * 2) return;   // 512 outputs
    int l = warp >> 8;
    int b = (warp >> 1) & 127;
    int h = warp & 1;
    const float* iv = instr + ((size_t)l * B_ + b) * 64;
    float s = iv[lane] * g_wea[l][64 + lane][h] + iv[lane + 32] * g_wea[l][96 + lane][h];
    #pragma unroll
    for (int o = 16; o; o >>= 1) s += __shfl_xor_sync(0xffffffffu, s, o);
    if (lane == 0) g_inse[l][b][h] = s;
}

// ---------------- ae: both layers, 4 edges per warp, EDGE-order output ----------------
__global__ void ae_kernel(const float* __restrict__ edge_attr,
                          const int* __restrict__ srcv,
                          const int* __restrict__ batch) {
    __shared__ float swe[L_][64][2];
    int tid = threadIdx.x;
    for (int i = tid; i < L_ * 64 * 2; i += 256) {
        int l = i >> 7, rem = i & 127;
        swe[l][rem >> 1][rem & 1] = g_wea[l][rem >> 1][rem & 1];
    }
    __syncthreads();
    int lane = tid & 31;
    int sub = lane >> 3, l8 = lane & 7;
    int nwarps = gridDim.x * 8;
    for (int warp = blockIdx.x * 8 + (tid >> 5); warp < E_ / 4; warp += nwarps) {
        int e = warp * 4 + sub;
        const float* row = edge_attr + (size_t)e * 64;
        float4 v0 = *(const float4*)(row + l8 * 4);
        float4 v1 = *(const float4*)(row + 32 + l8 * 4);
        float vv[8] = {v0.x, v0.y, v0.z, v0.w, v1.x, v1.y, v1.z, v1.w};
        int k0 = l8 * 4;
        float acc[4] = {0.f, 0.f, 0.f, 0.f};
        #pragma unroll
        for (int j = 0; j < 8; j++) {
            int k = (j < 4) ? (k0 + j) : (32 + k0 + j - 4);
            #pragma unroll
            for (int l = 0; l < 2; l++)
                #pragma unroll
                for (int h = 0; h < 2; h++)
                    acc[l * 2 + h] += vv[j] * swe[l][k][h];
        }
        #pragma unroll
        for (int o = 4; o; o >>= 1) {
            #pragma unroll
            for (int c = 0; c < 4; c++)
                acc[c] += __shfl_xor_sync(0xffffffffu, acc[c], o);
        }
        if (l8 == 0) {
            int b = batch[srcv[e]];
            g_aet[0][e] = make_float2(acc[0] + g_inse[0][b][0], acc[1] + g_inse[0][b][1]);
            g_aet[1][e] = make_float2(acc[2] + g_inse[1][b][0], acc[3] + g_inse[1][b][1]);
        }
    }
}

// ---------------- xl GEMM: 512 threads, 4x4 per-thread tile, 2 blocks/SM ----------------
#define GEMM_SHM ((128 * 68 + 128 * 128) * 4)
__global__ void __launch_bounds__(512, 2)
gemm_xl(const float* __restrict__ hin,
        const float* __restrict__ Wl,
        const float* __restrict__ ins,
        const int* __restrict__ batch,
        const float* __restrict__ attL,
        const float* __restrict__ attR,
        int bn,
        const float* __restrict__ gamma,
        const float* __restrict__ beta) {
    extern __shared__ float sh[];
    float* As = sh;                 // [128 k][68 m], k-major (transposed)
    float* Ws = sh + 128 * 68;      // [128 k][128 n], k-major
    __shared__ int   sbatch[64];
    __shared__ float s_sc[64], s_sh[64];
    int tid = threadIdx.x;
    int node0 = blockIdx.x * 64;
    int rows = min(64, N_ - node0);
    if (tid < 64) sbatch[tid] = (tid < rows) ? batch[node0 + tid] : 0;
    if (bn && tid >= 64 && tid < 128) {
        int c = tid - 64;
        float mu  = g_bnstats[c] * (1.f / N_);
        float var = g_bnstats[64 + c] * (1.f / N_) - mu * mu;
        float inv = rsqrtf(var + EPS_);
        float sc = inv * gamma[c];
        s_sc[c] = sc;
        s_sh[c] = beta[c] - mu * sc;
    }
    const float4* Wg = (const float4*)Wl;
    float4* Ws4 = (float4*)Ws;
    for (int i = tid; i < 128 * 32; i += 512) Ws4[i] = Wg[i];
    __syncthreads();
    for (int i = tid; i < 64 * 128; i += 512) {
        int m = i >> 7, k = i & 127;
        float v = 0.f;
        if (m < rows) {
            if (k < 64) {
                v = hin[(size_t)(node0 + m) * 64 + k];
                if (bn) { v = v * s_sc[k] + s_sh[k]; v = v > 0.f ? v : 0.f; }
            } else {
                v = ins[(size_t)sbatch[m] * 64 + (k - 64)];
            }
        }
        As[k * 68 + m] = v;
    }
    __syncthreads();
    int rt = tid >> 5;                 // 16 warps, 4 rows each
    int lane = tid & 31;
    float acc[4][4];
    #pragma unroll
    for (int r = 0; r < 4; r++)
        #pragma unroll
        for (int j = 0; j < 4; j++) acc[r][j] = 0.f;
    #pragma unroll 4
    for (int k = 0; k < 128; k++) {
        float4 a = *(const float4*)(As + k * 68 + rt * 4);   // warp-broadcast
        float4 b = *(const float4*)(Ws + k * 128 + lane * 4); // conflict-free
        float av[4] = {a.x, a.y, a.z, a.w};
        #pragma unroll
        for (int r = 0; r < 4; r++) {
            acc[r][0] += av[r] * b.x;
            acc[r][1] += av[r] * b.y;
            acc[r][2] += av[r] * b.z;
            acc[r][3] += av[r] * b.w;
        }
    }
    #pragma unroll
    for (int r = 0; r < 4; r++) {
        int m = rt * 4 + r;
        if (m < rows) {
            float4 v = {acc[r][0], acc[r][1], acc[r][2], acc[r][3]};
            *(float4*)(g_xl + (size_t)(node0 + m) * 128 + lane * 4) = v;
        }
    }
    // fused alr epilogue (fp32): al = xl.att_l, ar = xl.att_r per row
    float4 atl = *(const float4*)(attL + lane * 4);
    float4 atr = *(const float4*)(attR + lane * 4);
    #pragma unroll
    for (int r = 0; r < 4; r++) {
        float pl = acc[r][0] * atl.x + acc[r][1] * atl.y + acc[r][2] * atl.z + acc[r][3] * atl.w;
        float pr = acc[r][0] * atr.x + acc[r][1] * atr.y + acc[r][2] * atr.z + acc[r][3] * atr.w;
        #pragma unroll
        for (int o = 8; o; o >>= 1) {
            pl += __shfl_xor_sync(0xffffffffu, pl, o);
            pr += __shfl_xor_sync(0xffffffffu, pr, o);
        }
        float pl1 = __shfl_sync(0xffffffffu, pl, 16);
        float pr1 = __shfl_sync(0xffffffffu, pr, 16);
        int m = rt * 4 + r;
        if (lane == 0 && m < rows) {
            float4 v = {pl, pl1, pr, pr1};
            *(float4*)(g_alr + (size_t)(node0 + m) * 4) = v;
        }
    }
}

// ---------------- per-node aggregation: single pass, shift-free softmax, unroll 4 ----------------
__global__ void agg_kernel(int layer, const float* __restrict__ hin,
                           float* __restrict__ hout,
                           const float* __restrict__ bias, int do_stats,
                           int bn_resid,
                           const float* __restrict__ gamma,
                           const float* __restrict__ beta) {
    __shared__ float s_sum[64], s_sq[64], s_sc[64], s_sh[64];
    int tid = threadIdx.x;
    if (do_stats && tid < 64) { s_sum[tid] = 0.f; s_sq[tid] = 0.f; }
    if (bn_resid && tid < 64) {
        float mu  = g_bnstats[tid] * (1.f / N_);
        float var = g_bnstats[64 + tid] * (1.f / N_) - mu * mu;
        float inv = rsqrtf(var + EPS_);
        float sc = inv * gamma[tid];
        s_sc[tid] = sc;
        s_sh[tid] = beta[tid] - mu * sc;
    }
    __syncthreads();
    const unsigned FULL = 0xffffffffu;
    int lane = tid & 31;
    bool head1 = lane >= 16;
    int coff = lane * 4;
    const float2* aep = g_ae[layer];
    const float* bz = bias + layer * 64;
    int nwarps = gridDim.x * 8;
    for (int node = blockIdx.x * 8 + (tid >> 5); node < N_; node += nwarps) {
        int start = g_rowptr[node], end = g_rowptr[node + 1];
        float2 arr = *(const float2*)&g_alr[node * 4 + 2];
        float sum0 = 0.f, sum1 = 0.f;
        float acc0 = 0.f, acc1 = 0.f, acc2 = 0.f, acc3 = 0.f;
        int p = start;
        for (; p + 3 < end; p += 4) {
            int sA = g_csr_src[p],     sB = g_csr_src[p + 1];
            int sC = g_csr_src[p + 2], sD = g_csr_src[p + 3];
            float2 aeA = aep[p],     aeB = aep[p + 1];
            float2 aeC = aep[p + 2], aeD = aep[p + 3];
            float2 alA = *(const float2*)&g_alr[sA * 4];
            float2 alB = *(const float2*)&g_alr[sB * 4];
            float2 alC = *(const float2*)&g_alr[sC * 4];
            float2 alD = *(const float2*)&g_alr[sD * 4];
            float4 xA = *(const float4*)(g_xl + (size_t)sA * 128 + lane * 4);
            float4 xB = *(const float4*)(g_xl + (size_t)sB * 128 + lane * 4);
            float4 xC = *(const float4*)(g_xl + (size_t)sC * 128 + lane * 4);
            float4 xD = *(const float4*)(g_xl + (size_t)sD * 128 + lane * 4);
            float aA0 = alA.x + arr.x + aeA.x; aA0 = fmaxf(aA0, SLOPE * aA0);
            float aA1 = alA.y + arr.y + aeA.y; aA1 = fmaxf(aA1, SLOPE * aA1);
            float aB0 = alB.x + arr.x + aeB.x; aB0 = fmaxf(aB0, SLOPE * aB0);
            float aB1 = alB.y + arr.y + aeB.y; aB1 = fmaxf(aB1, SLOPE * aB1);
            float aC0 = alC.x + arr.x + aeC.x; aC0 = fmaxf(aC0, SLOPE * aC0);
            float aC1 = alC.y + arr.y + aeC.y; aC1 = fmaxf(aC1, SLOPE * aC1);
            float aD0 = alD.x + arr.x + aeD.x; aD0 = fmaxf(aD0, SLOPE * aD0);
            float aD1 = alD.y + arr.y + aeD.y; aD1 = fmaxf(aD1, SLOPE * aD1);
            float wA0 = __expf(aA0), wA1 = __expf(aA1);
            float wB0 = __expf(aB0), wB1 = __expf(aB1);
            float wC0 = __expf(aC0), wC1 = __expf(aC1);
            float wD0 = __expf(aD0), wD1 = __expf(aD1);
            sum0 += wA0 + wB0 + wC0 + wD0;
            sum1 += wA1 + wB1 + wC1 + wD1;
            float wA = head1 ? wA1 : wA0;
            float wB = head1 ? wB1 : wB0;
            float wC = head1 ? wC1 : wC0;
            float wD = head1 ? wD1 : wD0;
            acc0 += wA * xA.x + wB * xB.x + wC * xC.x + wD * xD.x;
            acc1 += wA * xA.y + wB * xB.y + wC * xC.y + wD * xD.y;
            acc2 += wA * xA.z + wB * xB.z + wC * xC.z + wD * xD.z;
            acc3 += wA * xA.w + wB * xB.w + wC * xC.w + wD * xD.w;
        }
        for (; p < end; p++) {
            int s = g_csr_src[p];
            float2 ae = aep[p];
            float2 al = *(const float2*)&g_alr[s * 4];
            float4 x = *(const float4*)(g_xl + (size_t)s * 128 + lane * 4);
            float a0 = al.x + arr.x + ae.x; a0 = fmaxf(a0, SLOPE * a0);
            float a1 = al.y + arr.y + ae.y; a1 = fmaxf(a1, SLOPE * a1);
            float w0 = __expf(a0), w1 = __expf(a1);
            sum0 += w0; sum1 += w1;
            float w = head1 ? w1 : w0;
            acc0 += w * x.x; acc1 += w * x.y; acc2 += w * x.z; acc3 += w * x.w;
        }
        float sc = head1 ? (1.f / (sum1 + 1e-16f)) : (1.f / (sum0 + 1e-16f));
        float o0 = acc0 * sc, o1 = acc1 * sc, o2 = acc2 * sc, o3 = acc3 * sc;
        float p0 = __shfl_xor_sync(FULL, o0, 16);
        float p1 = __shfl_xor_sync(FULL, o1, 16);
        float p2 = __shfl_xor_sync(FULL, o2, 16);
        float p3 = __shfl_xor_sync(FULL, o3, 16);
        if (!head1) {
            float4 hv = *(const float4*)(hin + (size_t)node * 64 + coff);
            if (bn_resid) {
                hv.x = fmaxf(hv.x * s_sc[coff + 0] + s_sh[coff + 0], 0.f);
                hv.y = fmaxf(hv.y * s_sc[coff + 1] + s_sh[coff + 1], 0.f);
                hv.z = fmaxf(hv.z * s_sc[coff + 2] + s_sh[coff + 2], 0.f);
                hv.w = fmaxf(hv.w * s_sc[coff + 3] + s_sh[coff + 3], 0.f);
            }
            float4 bv = *(const float4*)(bz + coff);
            float r0 = (o0 + p0) * 0.5f + bv.x + hv.x;
            float r1 = (o1 + p1) * 0.5f + bv.y + hv.y;
            float r2 = (o2 + p2) * 0.5f + bv.z + hv.z;
            float r3 = (o3 + p3) * 0.5f + bv.w + hv.w;
            float4 res = {r0, r1, r2, r3};
            *(float4*)(hout + (size_t)node * 64 + coff) = res;
            if (do_stats) {
                atomicAdd(&s_sum[coff + 0], r0); atomicAdd(&s_sq[coff + 0], r0 * r0);
                atomicAdd(&s_sum[coff + 1], r1); atomicAdd(&s_sq[coff + 1], r1 * r1);
                atomicAdd(&s_sum[coff + 2], r2); atomicAdd(&s_sq[coff + 2], r2 * r2);
                atomicAdd(&s_sum[coff + 3], r3); atomicAdd(&s_sq[coff + 3], r3 * r3);
            }
        }
    }
    if (do_stats) {
        __syncthreads();
        if (tid < 64) {
            atomicAdd(&g_bnstats[tid],      s_sum[tid]);
            atomicAdd(&g_bnstats[64 + tid], s_sq[tid]);
        }
    }
}

// ---------------- launch: s2 = setup1->setup2->ae->gemm0 ; main = hist->scan->scatter ----------------
extern "C" void kernel_launch(void* const* d_in, const int* in_sizes, int n_in,
                              void* d_out, int out_size) {
    const float* x         = (const float*)d_in[0];
    const int*   eidx      = (const int*)d_in[1];
    const float* edge_attr = (const float*)d_in[2];
    const float* instr     = (const float*)d_in[3];
    const int*   batch     = (const int*)d_in[4];
    const float* W_l       = (const float*)d_in[5];
    const float* W_e       = (const float*)d_in[6];
    const float* att_l     = (const float*)d_in[7];
    const float* att_r     = (const float*)d_in[8];
    const float* att_e     = (const float*)d_in[9];
    const float* bias      = (const float*)d_in[10];
    const float* bn_gamma  = (const float*)d_in[11];
    const float* bn_beta   = (const float*)d_in[12];
    float* out = (float*)d_out;

    const int* src = eidx;
    const int* dst = eidx + E_;

    float* h_ptr = nullptr;
    cudaGetSymbolAddress((void**)&h_ptr, g_h);
    cudaFuncSetAttribute(gemm_xl, cudaFuncAttributeMaxDynamicSharedMemorySize, GEMM_SHM);

    cudaStream_t s2;
    cudaStreamCreateWithFlags(&s2, cudaStreamNonBlocking);
    cudaEvent_t e1, eA, e2;
    cudaEventCreateWithFlags(&e1, cudaEventDisableTiming);
    cudaEventCreateWithFlags(&eA, cudaEventDisableTiming);
    cudaEventCreateWithFlags(&e2, cudaEventDisableTiming);

    cudaEventRecord(e1, 0);
    cudaStreamWaitEvent(s2, e1, 0);

    // s2: edge-weight setup (multi-block) -> ae (edge order) -> gemm0
    setup1_kernel<<<64, 256, 0, s2>>>(W_e, att_e);                 // launch 1
    setup2_kernel<<<64, 256, 0, s2>>>(instr);                      // launch 2
    ae_kernel<<<592, 256, 0, s2>>>(edge_attr, src, batch);         // launch 3
    cudaEventRecord(eA, s2);
    gemm_xl<<<(N_ + 63) / 64, 512, GEMM_SHM, s2>>>(x, W_l, instr, batch,
                                                   att_l, att_r, 0, nullptr, nullptr); // launch 4 (ncu)
    cudaEventRecord(e2, s2);

    // main: CSR build; scatter also permutes ae values (needs eA)
    hist_kernel<<<(E_ + 255) / 256, 256>>>(dst);                   // launch 5
    scan_kernel<<<1, 1024>>>();                                    // launch 6
    cudaStreamWaitEvent(0, eA, 0);
    scatter_kernel<<<(E_ + 255) / 256, 256>>>(src, dst);           // launch 7
    cudaStreamWaitEvent(0, e2, 0);     // join gemm0

    // layer 0 aggregation (collect BN stats)
    agg_kernel<<<1280, 256>>>(0, x, h_ptr, bias, 1, 0, nullptr, nullptr);

    // layer 1: GEMM with fused BN+relu on input, agg with fused BN+relu on residual
    gemm_xl<<<(N_ + 63) / 64, 512, GEMM_SHM>>>(h_ptr, W_l + 128 * 128, instr + B_ * 64, batch,
                                               att_l + 128, att_r + 128, 1, bn_gamma, bn_beta);
    agg_kernel<<<1280, 256>>>(1, h_ptr, out, bias, 0, 1, bn_gamma, bn_beta);
}

// round 16
// speedup vs baseline: 1.4696x; 1.4696x over previous
#include <cuda_runtime.h>
#include <cuda_bf16.h>
#include <mma.h>
#include <cstdint>

using namespace nvcuda;

#define N_   20000
#define E_   320000
#define B_   128
#define L_   2
#define SLOPE 0.2f
#define EPS_  1e-5f

// ---------------- scratch (static device allocations) ----------------
__device__ int   g_counts[N_];        // zero at load; re-zeroed by scan each call
__device__ int   g_rowptr[N_ + 1];
__device__ int   g_cursor[N_];
__device__ int   g_csr_src[E_];

__device__ float g_wea[L_][128][2];   // collapsed W_e * att_e
__device__ float g_inse[L_][B_][2];   // ins part of ae per graph

__device__ float2 g_aet[L_][E_];      // edge attention term, EDGE order (pre-permute)
__device__ float2 g_ae[L_][E_];       // edge attention term, CSR order (post-permute)
__device__ float g_xl[(size_t)N_ * 128];
__device__ float g_alr[N_ * 4];       // al0, al1, ar0, ar1
__device__ float g_h[(size_t)N_ * 64];
__device__ float g_bnstats[128];      // sum[64], sumsq[64]; re-zeroed by scan

// ---------------- CSR build ----------------
__global__ void hist_kernel(const int* __restrict__ dst) {
    int i = blockIdx.x * blockDim.x + threadIdx.x;
    if (i < E_) atomicAdd(&g_counts[dst[i]], 1);
}

__global__ void scan_kernel() {
    __shared__ int sums[1024];
    const int C = 20;
    int t = threadIdx.x;
    int base = t * C;
    int vals[C];
    int run = 0;
    #pragma unroll
    for (int i = 0; i < C; i++) {
        int idx = base + i;
        int v = (idx < N_) ? g_counts[idx] : 0;
        run += v;
        vals[i] = run;
    }
    sums[t] = run;
    __syncthreads();
    for (int o = 1; o < 1024; o <<= 1) {
        int x = (t >= o) ? sums[t - o] : 0;
        __syncthreads();
        sums[t] += x;
        __syncthreads();
    }
    int off = sums[t] - run;
    if (t == 0) g_rowptr[0] = 0;
    #pragma unroll
    for (int i = 0; i < C; i++) {
        int idx = base + i;
        if (idx < N_) {
            int incl = off + vals[i];
            int cnt  = vals[i] - (i ? vals[i - 1] : 0);
            g_rowptr[idx + 1] = incl;
            g_cursor[idx]     = incl - cnt;
            g_counts[idx]     = 0;
        }
    }
    if (t < 128) g_bnstats[t] = 0.f;
}

__global__ void scatter_kernel(const int* __restrict__ src, const int* __restrict__ dst) {
    int i = blockIdx.x * blockDim.x + threadIdx.x;
    if (i < E_) {
        int d = dst[i];
        float2 a0 = g_aet[0][i];
        float2 a1 = g_aet[1][i];
        int pos = atomicAdd(&g_cursor[d], 1);
        g_csr_src[pos] = src[i];
        g_ae[0][pos] = a0;
        g_ae[1][pos] = a1;
    }
}

// ---------------- setup1/setup2 ----------------
__global__ void setup1_kernel(const float* __restrict__ W_e,
                              const float* __restrict__ att_e) {
    int warp = (blockIdx.x * blockDim.x + threadIdx.x) >> 5;
    int lane = threadIdx.x & 31;
    if (warp >= L_ * 128 * 2) return;
    int l = warp >> 8;
    int k = (warp >> 1) & 127;
    int h = warp & 1;
    const float* wrow = W_e + ((size_t)l * 128 + k) * 128 + h * 64;
    const float* arow = att_e + l * 128 + h * 64;
    float s = wrow[lane] * arow[lane] + wrow[lane + 32] * arow[lane + 32];
    #pragma unroll
    for (int o = 16; o; o >>= 1) s += __shfl_xor_sync(0xffffffffu, s, o);
    if (lane == 0) g_wea[l][k][h] = s;
}

__global__ void setup2_kernel(const float* __restrict__ instr) {
    int warp = (blockIdx.x * blockDim.x + threadIdx.x) >> 5;
    int lane = threadIdx.x & 31;
    if (warp >= L_ * B_ * 2) return;
    int l = warp >> 8;
    int b = (warp >> 1) & 127;
    int h = warp & 1;
    const float* iv = instr + ((size_t)l * B_ + b) * 64;
    float s = iv[lane] * g_wea[l][64 + lane][h] + iv[lane + 32] * g_wea[l][96 + lane][h];
    #pragma unroll
    for (int o = 16; o; o >>= 1) s += __shfl_xor_sync(0xffffffffu, s, o);
    if (lane == 0) g_inse[l][b][h] = s;
}

// ---------------- ae ----------------
__global__ void ae_kernel(const float* __restrict__ edge_attr,
                          const int* __restrict__ srcv,
                          const int* __restrict__ batch) {
    __shared__ float swe[L_][64][2];
    int tid = threadIdx.x;
    for (int i = tid; i < L_ * 64 * 2; i += 256) {
        int l = i >> 7, rem = i & 127;
        swe[l][rem >> 1][rem & 1] = g_wea[l][rem >> 1][rem & 1];
    }
    __syncthreads();
    int lane = tid & 31;
    int sub = lane >> 3, l8 = lane & 7;
    int nwarps = gridDim.x * 8;
    for (int warp = blockIdx.x * 8 + (tid >> 5); warp < E_ / 4; warp += nwarps) {
        int e = warp * 4 + sub;
        const float* row = edge_attr + (size_t)e * 64;
        float4 v0 = *(const float4*)(row + l8 * 4);
        float4 v1 = *(const float4*)(row + 32 + l8 * 4);
        float vv[8] = {v0.x, v0.y, v0.z, v0.w, v1.x, v1.y, v1.z, v1.w};
        int k0 = l8 * 4;
        float acc[4] = {0.f, 0.f, 0.f, 0.f};
        #pragma unroll
        for (int j = 0; j < 8; j++) {
            int k = (j < 4) ? (k0 + j) : (32 + k0 + j - 4);
            #pragma unroll
            for (int l = 0; l < 2; l++)
                #pragma unroll
                for (int h = 0; h < 2; h++)
                    acc[l * 2 + h] += vv[j] * swe[l][k][h];
        }
        #pragma unroll
        for (int o = 4; o; o >>= 1) {
            #pragma unroll
            for (int c = 0; c < 4; c++)
                acc[c] += __shfl_xor_sync(0xffffffffu, acc[c], o);
        }
        if (l8 == 0) {
            int b = batch[srcv[e]];
            g_aet[0][e] = make_float2(acc[0] + g_inse[0][b][0], acc[1] + g_inse[0][b][1]);
            g_aet[1][e] = make_float2(acc[2] + g_inse[1][b][0], acc[3] + g_inse[1][b][1]);
        }
    }
}

// ---------------- WMMA bf16 GEMM: 64x128x128 tile, HMMA tensor pipe ----------------
// smem layout (bytes): A bf16 [64][136] @0 (17408), B bf16 [128][136] @17408 (34816)
// stage fp32 [64][132] reuses @0 after MMA (33792 < 52224)
#define A_LD   136
#define B_LD   136
#define S_LD   132
#define B_OFF  (64 * A_LD)                       // in bf16 elements
#define GEMM_SHM ((64 * A_LD + 128 * B_LD) * 2)  // 52224 bytes

__global__ void __launch_bounds__(256, 2)
gemm_wmma(const float* __restrict__ hin,
          const float* __restrict__ Wl,
          const float* __restrict__ ins,
          const int* __restrict__ batch,
          const float* __restrict__ attL,
          const float* __restrict__ attR,
          int bn,
          const float* __restrict__ gamma,
          const float* __restrict__ beta) {
    extern __shared__ __nv_bfloat16 shb[];
    __nv_bfloat16* As = shb;                 // [64][136]
    __nv_bfloat16* Bs = shb + B_OFF;         // [128][136]
    float* stage = (float*)shb;              // [64][132], reused after MMA
    __shared__ int   sbatch[64];
    __shared__ float s_sc[64], s_sh[64];
    int tid = threadIdx.x;                   // 256 threads = 8 warps
    int node0 = blockIdx.x * 64;
    int rows = min(64, N_ - node0);
    if (tid < 64) sbatch[tid] = (tid < rows) ? batch[node0 + tid] : 0;
    if (bn && tid >= 64 && tid < 128) {
        int c = tid - 64;
        float mu  = g_bnstats[c] * (1.f / N_);
        float var = g_bnstats[64 + c] * (1.f / N_) - mu * mu;
        float inv = rsqrtf(var + EPS_);
        float sc = inv * gamma[c];
        s_sc[c] = sc;
        s_sh[c] = beta[c] - mu * sc;
    }
    __syncthreads();
    // fill A: [m][k] bf16, BN+relu fused on h-half for layer 1
    for (int idx = tid; idx < 64 * 128; idx += 256) {
        int m = idx >> 7, k = idx & 127;
        float v = 0.f;
        if (m < rows) {
            if (k < 64) {
                v = hin[(size_t)(node0 + m) * 64 + k];
                if (bn) { v = v * s_sc[k] + s_sh[k]; v = v > 0.f ? v : 0.f; }
            } else {
                v = ins[(size_t)sbatch[m] * 64 + (k - 64)];
            }
        }
        As[m * A_LD + k] = __float2bfloat16(v);
    }
    // fill B: [k][n] bf16, direct from W (row-major k x n) — coalesced
    for (int idx = tid; idx < 128 * 128; idx += 256) {
        int k = idx >> 7, n = idx & 127;
        Bs[k * B_LD + n] = __float2bfloat16(Wl[(size_t)k * 128 + n]);
    }
    __syncthreads();

    // MMA: warp (wm, wn): rows 16*wm, cols 64*wn (4 subtiles of 16)
    int wid = tid >> 5, lane = tid & 31;
    int wm = wid & 3, wn = wid >> 2;
    wmma::fragment<wmma::accumulator, 16, 16, 16, float> acc[4];
    #pragma unroll
    for (int j = 0; j < 4; j++) wmma::fill_fragment(acc[j], 0.f);
    #pragma unroll
    for (int k = 0; k < 8; k++) {
        wmma::fragment<wmma::matrix_a, 16, 16, 16, __nv_bfloat16, wmma::row_major> af;
        wmma::load_matrix_sync(af, As + (wm * 16) * A_LD + k * 16, A_LD);
        #pragma unroll
        for (int j = 0; j < 4; j++) {
            wmma::fragment<wmma::matrix_b, 16, 16, 16, __nv_bfloat16, wmma::row_major> bf;
            wmma::load_matrix_sync(bf, Bs + (k * 16) * B_LD + wn * 64 + j * 16, B_LD);
            wmma::mma_sync(acc[j], af, bf, acc[j]);
        }
    }
    __syncthreads();   // done reading A/B; reuse smem as stage
    #pragma unroll
    for (int j = 0; j < 4; j++)
        wmma::store_matrix_sync(stage + (wm * 16) * S_LD + wn * 64 + j * 16,
                                acc[j], S_LD, wmma::mem_row_major);
    __syncthreads();

    // epilogue: alr dots + coalesced xl writeback (R13 pattern, reading stage)
    float4 atl = *(const float4*)(attL + lane * 4);
    float4 atr = *(const float4*)(attR + lane * 4);
    int rt = wid;                       // 8 warps x 8 rows
    #pragma unroll
    for (int r = 0; r < 8; r++) {
        int m = rt * 8 + r;
        float4 v = *(const float4*)(stage + m * S_LD + lane * 4);
        float pl = v.x * atl.x + v.y * atl.y + v.z * atl.z + v.w * atl.w;
        float pr = v.x * atr.x + v.y * atr.y + v.z * atr.z + v.w * atr.w;
        #pragma unroll
        for (int o = 8; o; o >>= 1) {
            pl += __shfl_xor_sync(0xffffffffu, pl, o);
            pr += __shfl_xor_sync(0xffffffffu, pr, o);
        }
        float pl1 = __shfl_sync(0xffffffffu, pl, 16);
        float pr1 = __shfl_sync(0xffffffffu, pr, 16);
        if (lane == 0 && m < rows) {
            float4 w = {pl, pl1, pr, pr1};
            *(float4*)(g_alr + (size_t)(node0 + m) * 4) = w;
        }
    }
    for (int idx = tid; idx < 64 * 128; idx += 256) {
        int m = idx >> 7, c = idx & 127;
        if (m < rows)
            g_xl[(size_t)(node0 + m) * 128 + c] = stage[m * S_LD + c];
    }
}

// ---------------- per-node aggregation (unchanged from R13) ----------------
__global__ void agg_kernel(int layer, const float* __restrict__ hin,
                           float* __restrict__ hout,
                           const float* __restrict__ bias, int do_stats,
                           int bn_resid,
                           const float* __restrict__ gamma,
                           const float* __restrict__ beta) {
    __shared__ float s_sum[64], s_sq[64], s_sc[64], s_sh[64];
    int tid = threadIdx.x;
    if (do_stats && tid < 64) { s_sum[tid] = 0.f; s_sq[tid] = 0.f; }
    if (bn_resid && tid < 64) {
        float mu  = g_bnstats[tid] * (1.f / N_);
        float var = g_bnstats[64 + tid] * (1.f / N_) - mu * mu;
        float inv = rsqrtf(var + EPS_);
        float sc = inv * gamma[tid];
        s_sc[tid] = sc;
        s_sh[tid] = beta[tid] - mu * sc;
    }
    __syncthreads();
    const unsigned FULL = 0xffffffffu;
    int lane = tid & 31;
    bool head1 = lane >= 16;
    int coff = lane * 4;
    const float2* aep = g_ae[layer];
    const float* bz = bias + layer * 64;
    int nwarps = gridDim.x * 8;
    for (int node = blockIdx.x * 8 + (tid >> 5); node < N_; node += nwarps) {
        int start = g_rowptr[node], end = g_rowptr[node + 1];
        float2 arr = *(const float2*)&g_alr[node * 4 + 2];
        float sum0 = 0.f, sum1 = 0.f;
        float acc0 = 0.f, acc1 = 0.f, acc2 = 0.f, acc3 = 0.f;
        int p = start;
        for (; p + 3 < end; p += 4) {
            int sA = g_csr_src[p],     sB = g_csr_src[p + 1];
            int sC = g_csr_src[p + 2], sD = g_csr_src[p + 3];
            float2 aeA = aep[p],     aeB = aep[p + 1];
            float2 aeC = aep[p + 2], aeD = aep[p + 3];
            float2 alA = *(const float2*)&g_alr[sA * 4];
            float2 alB = *(const float2*)&g_alr[sB * 4];
            float2 alC = *(const float2*)&g_alr[sC * 4];
            float2 alD = *(const float2*)&g_alr[sD * 4];
            float4 xA = *(const float4*)(g_xl + (size_t)sA * 128 + lane * 4);
            float4 xB = *(const float4*)(g_xl + (size_t)sB * 128 + lane * 4);
            float4 xC = *(const float4*)(g_xl + (size_t)sC * 128 + lane * 4);
            float4 xD = *(const float4*)(g_xl + (size_t)sD * 128 + lane * 4);
            float aA0 = alA.x + arr.x + aeA.x; aA0 = fmaxf(aA0, SLOPE * aA0);
            float aA1 = alA.y + arr.y + aeA.y; aA1 = fmaxf(aA1, SLOPE * aA1);
            float aB0 = alB.x + arr.x + aeB.x; aB0 = fmaxf(aB0, SLOPE * aB0);
            float aB1 = alB.y + arr.y + aeB.y; aB1 = fmaxf(aB1, SLOPE * aB1);
            float aC0 = alC.x + arr.x + aeC.x; aC0 = fmaxf(aC0, SLOPE * aC0);
            float aC1 = alC.y + arr.y + aeC.y; aC1 = fmaxf(aC1, SLOPE * aC1);
            float aD0 = alD.x + arr.x + aeD.x; aD0 = fmaxf(aD0, SLOPE * aD0);
            float aD1 = alD.y + arr.y + aeD.y; aD1 = fmaxf(aD1, SLOPE * aD1);
            float wA0 = __expf(aA0), wA1 = __expf(aA1);
            float wB0 = __expf(aB0), wB1 = __expf(aB1);
            float wC0 = __expf(aC0), wC1 = __expf(aC1);
            float wD0 = __expf(aD0), wD1 = __expf(aD1);
            sum0 += wA0 + wB0 + wC0 + wD0;
            sum1 += wA1 + wB1 + wC1 + wD1;
            float wA = head1 ? wA1 : wA0;
            float wB = head1 ? wB1 : wB0;
            float wC = head1 ? wC1 : wC0;
            float wD = head1 ? wD1 : wD0;
            acc0 += wA * xA.x + wB * xB.x + wC * xC.x + wD * xD.x;
            acc1 += wA * xA.y + wB * xB.y + wC * xC.y + wD * xD.y;
            acc2 += wA * xA.z + wB * xB.z + wC * xC.z + wD * xD.z;
            acc3 += wA * xA.w + wB * xB.w + wC * xC.w + wD * xD.w;
        }
        for (; p < end; p++) {
            int s = g_csr_src[p];
            float2 ae = aep[p];
            float2 al = *(const float2*)&g_alr[s * 4];
            float4 x = *(const float4*)(g_xl + (size_t)s * 128 + lane * 4);
            float a0 = al.x + arr.x + ae.x; a0 = fmaxf(a0, SLOPE * a0);
            float a1 = al.y + arr.y + ae.y; a1 = fmaxf(a1, SLOPE * a1);
            float w0 = __expf(a0), w1 = __expf(a1);
            sum0 += w0; sum1 += w1;
            float w = head1 ? w1 : w0;
            acc0 += w * x.x; acc1 += w * x.y; acc2 += w * x.z; acc3 += w * x.w;
        }
        float sc = head1 ? (1.f / (sum1 + 1e-16f)) : (1.f / (sum0 + 1e-16f));
        float o0 = acc0 * sc, o1 = acc1 * sc, o2 = acc2 * sc, o3 = acc3 * sc;
        float p0 = __shfl_xor_sync(FULL, o0, 16);
        float p1 = __shfl_xor_sync(FULL, o1, 16);
        float p2 = __shfl_xor_sync(FULL, o2, 16);
        float p3 = __shfl_xor_sync(FULL, o3, 16);
        if (!head1) {
            float4 hv = *(const float4*)(hin + (size_t)node * 64 + coff);
            if (bn_resid) {
                hv.x = fmaxf(hv.x * s_sc[coff + 0] + s_sh[coff + 0], 0.f);
                hv.y = fmaxf(hv.y * s_sc[coff + 1] + s_sh[coff + 1], 0.f);
                hv.z = fmaxf(hv.z * s_sc[coff + 2] + s_sh[coff + 2], 0.f);
                hv.w = fmaxf(hv.w * s_sc[coff + 3] + s_sh[coff + 3], 0.f);
            }
            float4 bv = *(const float4*)(bz + coff);
            float r0 = (o0 + p0) * 0.5f + bv.x + hv.x;
            float r1 = (o1 + p1) * 0.5f + bv.y + hv.y;
            float r2 = (o2 + p2) * 0.5f + bv.z + hv.z;
            float r3 = (o3 + p3) * 0.5f + bv.w + hv.w;
            float4 res = {r0, r1, r2, r3};
            *(float4*)(hout + (size_t)node * 64 + coff) = res;
            if (do_stats) {
                atomicAdd(&s_sum[coff + 0], r0); atomicAdd(&s_sq[coff + 0], r0 * r0);
                atomicAdd(&s_sum[coff + 1], r1); atomicAdd(&s_sq[coff + 1], r1 * r1);
                atomicAdd(&s_sum[coff + 2], r2); atomicAdd(&s_sq[coff + 2], r2 * r2);
                atomicAdd(&s_sum[coff + 3], r3); atomicAdd(&s_sq[coff + 3], r3 * r3);
            }
        }
    }
    if (do_stats) {
        __syncthreads();
        if (tid < 64) {
            atomicAdd(&g_bnstats[tid],      s_sum[tid]);
            atomicAdd(&g_bnstats[64 + tid], s_sq[tid]);
        }
    }
}

// ---------------- launch ----------------
extern "C" void kernel_launch(void* const* d_in, const int* in_sizes, int n_in,
                              void* d_out, int out_size) {
    const float* x         = (const float*)d_in[0];
    const int*   eidx      = (const int*)d_in[1];
    const float* edge_attr = (const float*)d_in[2];
    const float* instr     = (const float*)d_in[3];
    const int*   batch     = (const int*)d_in[4];
    const float* W_l       = (const float*)d_in[5];
    const float* W_e       = (const float*)d_in[6];
    const float* att_l     = (const float*)d_in[7];
    const float* att_r     = (const float*)d_in[8];
    const float* att_e     = (const float*)d_in[9];
    const float* bias      = (const float*)d_in[10];
    const float* bn_gamma  = (const float*)d_in[11];
    const float* bn_beta   = (const float*)d_in[12];
    float* out = (float*)d_out;

    const int* src = eidx;
    const int* dst = eidx + E_;

    float* h_ptr = nullptr;
    cudaGetSymbolAddress((void**)&h_ptr, g_h);
    cudaFuncSetAttribute(gemm_wmma, cudaFuncAttributeMaxDynamicSharedMemorySize, GEMM_SHM);

    cudaStream_t s2;
    cudaStreamCreateWithFlags(&s2, cudaStreamNonBlocking);
    cudaEvent_t e1, eA, e2;
    cudaEventCreateWithFlags(&e1, cudaEventDisableTiming);
    cudaEventCreateWithFlags(&eA, cudaEventDisableTiming);
    cudaEventCreateWithFlags(&e2, cudaEventDisableTiming);

    cudaEventRecord(e1, 0);
    cudaStreamWaitEvent(s2, e1, 0);

    // s2: edge-weight setup -> ae (edge order) -> gemm0 (WMMA)
    setup1_kernel<<<64, 256, 0, s2>>>(W_e, att_e);
    setup2_kernel<<<64, 256, 0, s2>>>(instr);
    ae_kernel<<<592, 256, 0, s2>>>(edge_attr, src, batch);
    cudaEventRecord(eA, s2);
    gemm_wmma<<<(N_ + 63) / 64, 256, GEMM_SHM, s2>>>(x, W_l, instr, batch,
                                                     att_l, att_r, 0, nullptr, nullptr);
    cudaEventRecord(e2, s2);

    // main: CSR build; scatter also permutes ae values (needs eA)
    hist_kernel<<<(E_ + 255) / 256, 256>>>(dst);
    scan_kernel<<<1, 1024>>>();
    cudaStreamWaitEvent(0, eA, 0);
    scatter_kernel<<<(E_ + 255) / 256, 256>>>(src, dst);
    cudaStreamWaitEvent(0, e2, 0);     // join gemm0

    // layer 0 aggregation (collect BN stats)
    agg_kernel<<<1280, 256>>>(0, x, h_ptr, bias, 1, 0, nullptr, nullptr);

    // layer 1: WMMA GEMM with fused BN+relu on input, agg with fused BN+relu on residual
    gemm_wmma<<<(N_ + 63) / 64, 256, GEMM_SHM>>>(h_ptr, W_l + 128 * 128, instr + B_ * 64, batch,
                                                 att_l + 128, att_r + 128, 1, bn_gamma, bn_beta);
    agg_kernel<<<1280, 256>>>(1, h_ptr, out, bias, 0, 1, bn_gamma, bn_beta);
}